// round 14
// baseline (speedup 1.0000x reference)
#include <cuda_runtime.h>
#include <cuda_fp16.h>
#include <cstdint>

// ---------------- problem constants -----------------------------------------
#define MROWS 8192      // B*C = 32*256
#define VIN   6890
#define VOUT  1723
#define KPAD  6912      // 108 * 64
#define NPAD  1792      // 14 * 128

// fp16 scratch for M only (x is consumed fp32 directly by the GEMM)
__device__ __align__(16) __half g_Mh[(size_t)NPAD * KPAD];   // ~25 MB

// ---------------- vectorized fp32 -> fp16 conversion for M -------------------
__global__ void convert_m_v(const float* __restrict__ m) {
    int k8 = blockIdx.x * blockDim.x + threadIdx.x;
    if (k8 >= KPAD / 8) return;
    int row = blockIdx.y;                             // 0..NPAD-1
    int k = k8 * 8;
    __align__(16) __half h[8];
    if (row < VOUT) {
        const float* src = m + (size_t)row * VIN + k;
        if (k + 8 <= VIN) {
            #pragma unroll
            for (int j = 0; j < 4; ++j) {
                float2 f = *reinterpret_cast<const float2*>(src + 2 * j);
                h[2 * j]     = __float2half(f.x);
                h[2 * j + 1] = __float2half(f.y);
            }
        } else {
            #pragma unroll
            for (int j = 0; j < 8; ++j)
                h[j] = (k + j < VIN) ? __float2half(src[j]) : __float2half(0.0f);
        }
    } else {
        #pragma unroll
        for (int j = 0; j < 8; ++j) h[j] = __float2half(0.0f);
    }
    *reinterpret_cast<uint4*>(&g_Mh[(size_t)row * KPAD + k]) =
        *reinterpret_cast<const uint4*>(h);
}

// ---------------- PTX helpers -----------------------------------------------
__device__ __forceinline__ void cp_async16(void* smem, const void* gmem) {
    uint32_t s = (uint32_t)__cvta_generic_to_shared(smem);
    asm volatile("cp.async.cg.shared.global [%0], [%1], 16;\n" :: "r"(s), "l"(gmem));
}
__device__ __forceinline__ void cp_commit() {
    asm volatile("cp.async.commit_group;\n" ::: "memory");
}
template<int N> __device__ __forceinline__ void cp_wait() {
    asm volatile("cp.async.wait_group %0;\n" :: "n"(N) : "memory");
}
__device__ __forceinline__ void ldsm_x4(uint32_t& r0, uint32_t& r1, uint32_t& r2,
                                        uint32_t& r3, const void* p) {
    uint32_t s = (uint32_t)__cvta_generic_to_shared(p);
    asm volatile("ldmatrix.sync.aligned.m8n8.x4.shared.b16 {%0,%1,%2,%3}, [%4];\n"
                 : "=r"(r0), "=r"(r1), "=r"(r2), "=r"(r3) : "r"(s));
}
__device__ __forceinline__ void mma16816(float* c, const uint32_t* a, const uint32_t* b) {
    asm volatile("mma.sync.aligned.m16n8k16.row.col.f32.f16.f16.f32 "
                 "{%0,%1,%2,%3}, {%4,%5,%6,%7}, {%8,%9}, {%0,%1,%2,%3};\n"
                 : "+f"(c[0]), "+f"(c[1]), "+f"(c[2]), "+f"(c[3])
                 : "r"(a[0]), "r"(a[1]), "r"(a[2]), "r"(a[3]),
                   "r"(b[0]), "r"(b[1]));
}

// ---------------- GEMM: C[8192,1723] = x(f32, converted in-kernel) * Mh^T ----
// R11 core (CTA 128x128, 4 warps 64x64, 3-stage, occ 2) with the fp32->fp16
// conversion of A fused into the stage fill (LDG.64 -> cvt -> STS.128),
// split into two waves interleaved with the MMA blocks for latency cover.
#define BM 128
#define BN 128
#define KC 64
#define STAGES 3
#define NSTG (KPAD / KC)        // 108
#define LDS_K 72                // 64 + 8 pad halves: LDSM conflict-free
#define A_HALVES (BM * LDS_K)   // 9216
#define B_HALVES (BN * LDS_K)   // 9216
#define STG_HALVES (A_HALVES + B_HALVES)       // 18432
#define SMEM_BYTES (STAGES * STG_HALVES * 2)   // 110,592 B per CTA

__global__ __launch_bounds__(128, 2) void gemm_kernel(const float* __restrict__ xg,
                                                      float* __restrict__ out) {
    extern __shared__ __align__(16) __half sm[];

    const int tid  = threadIdx.x;
    const int lane = tid & 31;
    const int warp = tid >> 5;    // 0..3
    const int wm   = warp & 1;    // m offset wm*64
    const int wn   = warp >> 1;   // n offset wn*64
    const int bn   = blockIdx.x * BN;
    const int bm   = blockIdx.y * BM;

    const __half* Bg = g_Mh + (size_t)bn * KPAD;

    // per-thread A/B fill map: k16 = tid&7 (fixed columns), rows r0 + 16j
    const int k16 = tid & 7;
    const int r0  = tid >> 3;

    // ---- B fill: cp.async fp16 from g_Mh --------------------------------
    auto loadB = [&](int s) {
        __half* bS = sm + (s % STAGES) * STG_HALVES + A_HALVES;
        const int kb = s * KC;
        #pragma unroll
        for (int j = 0; j < 8; ++j)
            cp_async16(bS + (r0 + 16 * j) * LDS_K + k16 * 8,
                       Bg + (size_t)(r0 + 16 * j) * KPAD + kb + k16 * 8);
    };

    // ---- A fill waves: LDG fp32 -> regs, later cvt -> STS fp16 -----------
    // wave w covers rows r0 + 16*(4w+j), j=0..3; 32 floats in rb[16] float2.
    auto loadA_wave = [&](int s, int w, float2* rb) {
        const int gk = s * KC + k16 * 8;
        if (gk + 8 <= VIN) {
            #pragma unroll
            for (int j = 0; j < 4; ++j) {
                const float* src =
                    xg + (size_t)(bm + r0 + 16 * (4 * w + j)) * VIN + gk;
                #pragma unroll
                for (int q = 0; q < 4; ++q)
                    rb[4 * j + q] = *reinterpret_cast<const float2*>(src + 2 * q);
            }
        } else {
            #pragma unroll
            for (int j = 0; j < 4; ++j) {
                const float* src =
                    xg + (size_t)(bm + r0 + 16 * (4 * w + j)) * VIN + gk;
                #pragma unroll
                for (int q = 0; q < 4; ++q) {
                    float a = (gk + 2 * q     < VIN) ? src[2 * q]     : 0.0f;
                    float b = (gk + 2 * q + 1 < VIN) ? src[2 * q + 1] : 0.0f;
                    rb[4 * j + q] = make_float2(a, b);
                }
            }
        }
    };
    auto storeA_wave = [&](int s, int w, const float2* rb) {
        __half* aD = sm + (s % STAGES) * STG_HALVES;
        #pragma unroll
        for (int j = 0; j < 4; ++j) {
            __align__(16) __half h[8];
            #pragma unroll
            for (int q = 0; q < 4; ++q) {
                float2 f = rb[4 * j + q];
                h[2 * q]     = __float2half(f.x);
                h[2 * q + 1] = __float2half(f.y);
            }
            *reinterpret_cast<uint4*>(
                aD + (r0 + 16 * (4 * w + j)) * LDS_K + k16 * 8) =
                *reinterpret_cast<const uint4*>(h);
        }
    };
    auto fillA_sync = [&](int s) {   // prologue: load+store both waves
        float2 rb[16];
        loadA_wave(s, 0, rb); storeA_wave(s, 0, rb);
        loadA_wave(s, 1, rb); storeA_wave(s, 1, rb);
    };

    // ---- fragments (double-buffered, as in R11) ---------------------------
    uint32_t afr[2][4][4];
    uint32_t bfr[2][8][2];
    const int a_row    = wm * 64 + (lane & 15);
    const int a_colsel = (lane >> 4) * 8;
    const int b_row    = wn * 64 + (lane & 7) + ((lane >> 4) << 3);
    const int b_colsel = ((lane >> 3) & 1) << 3;

    auto loadFrags = [&](const __half* aS, const __half* bS, int ks, int buf) {
        const int kstep = ks * 16;
        #pragma unroll
        for (int i = 0; i < 4; ++i)
            ldsm_x4(afr[buf][i][0], afr[buf][i][1], afr[buf][i][2], afr[buf][i][3],
                    aS + (a_row + i * 16) * LDS_K + kstep + a_colsel);
        #pragma unroll
        for (int j = 0; j < 4; ++j) {
            uint32_t t0, t1, t2, t3;
            ldsm_x4(t0, t1, t2, t3,
                    bS + (b_row + j * 16) * LDS_K + kstep + b_colsel);
            bfr[buf][2 * j][0] = t0;     bfr[buf][2 * j][1] = t1;
            bfr[buf][2 * j + 1][0] = t2; bfr[buf][2 * j + 1][1] = t3;
        }
    };

    float acc[4][8][4];
    #pragma unroll
    for (int i = 0; i < 4; ++i)
        #pragma unroll
        for (int j = 0; j < 8; ++j)
            #pragma unroll
            for (int e = 0; e < 4; ++e) acc[i][j][e] = 0.0f;

    // prologue: stages 0,1
    fillA_sync(0); loadB(0); cp_commit();
    fillA_sync(1); loadB(1); cp_commit();
    cp_wait<1>();
    __syncthreads();               // stage 0 resident

    float2 rawA[16];
    for (int kt = 0; kt < NSTG; ++kt) {
        const bool doL = (kt + 2 < NSTG);
        if (doL) loadB(kt + 2);
        cp_commit();

        const __half* aS = sm + (kt % STAGES) * STG_HALVES;
        const __half* bS = aS + A_HALVES;

        loadFrags(aS, bS, 0, 0);
        if (doL) loadA_wave(kt + 2, 0, rawA);      // LDG wave 0 in flight
        loadFrags(aS, bS, 1, 1);
        #pragma unroll
        for (int i = 0; i < 4; ++i)                // MMA ks=0
            #pragma unroll
            for (int jn = 0; jn < 8; ++jn)
                mma16816(acc[i][jn], afr[0][i], bfr[0][jn]);
        loadFrags(aS, bS, 2, 0);
        #pragma unroll
        for (int i = 0; i < 4; ++i)                // MMA ks=1
            #pragma unroll
            for (int jn = 0; jn < 8; ++jn)
                mma16816(acc[i][jn], afr[1][i], bfr[1][jn]);
        if (doL) {
            storeA_wave(kt + 2, 0, rawA);          // wave 0 landed under ks0/1
            loadA_wave(kt + 2, 1, rawA);           // LDG wave 1 in flight
        }
        loadFrags(aS, bS, 3, 1);
        #pragma unroll
        for (int i = 0; i < 4; ++i)                // MMA ks=2
            #pragma unroll
            for (int jn = 0; jn < 8; ++jn)
                mma16816(acc[i][jn], afr[0][i], bfr[0][jn]);
        #pragma unroll
        for (int i = 0; i < 4; ++i)                // MMA ks=3
            #pragma unroll
            for (int jn = 0; jn < 8; ++jn)
                mma16816(acc[i][jn], afr[1][i], bfr[1][jn]);
        if (doL) storeA_wave(kt + 2, 1, rawA);     // wave 1 landed under ks2/3

        cp_wait<1>();
        __syncthreads();           // stage kt+1 resident; all warps done with kt
    }

    // epilogue: scalar fp32 guarded stores (VOUT=1723 odd)
    const int g  = lane >> 2;
    const int tc = lane & 3;
    #pragma unroll
    for (int i = 0; i < 4; ++i) {
        #pragma unroll
        for (int jn = 0; jn < 8; ++jn) {
            const int row = bm + wm * 64 + i * 16 + g;
            const int col = bn + wn * 64 + jn * 8 + tc * 2;
            if (col < VOUT)     out[(size_t)row * VOUT + col]           = acc[i][jn][0];
            if (col + 1 < VOUT) out[(size_t)row * VOUT + col + 1]       = acc[i][jn][1];
            if (col < VOUT)     out[(size_t)(row + 8) * VOUT + col]     = acc[i][jn][2];
            if (col + 1 < VOUT) out[(size_t)(row + 8) * VOUT + col + 1] = acc[i][jn][3];
        }
    }
}

// ---------------- entry ------------------------------------------------------
extern "C" void kernel_launch(void* const* d_in, const int* in_sizes, int n_in,
                              void* d_out, int out_size) {
    const float* x = (const float*)d_in[0];  // (32,256,6890) fp32
    const float* M = (const float*)d_in[1];  // (1723,6890) fp32
    float* out = (float*)d_out;              // (32,256,1723) fp32

    cudaFuncSetAttribute(gemm_kernel, cudaFuncAttributeMaxDynamicSharedMemorySize,
                         SMEM_BYTES);

    convert_m_v<<<dim3((KPAD / 8 + 127) / 128, NPAD), 128>>>(M);
    gemm_kernel<<<dim3(NPAD / BN, MROWS / BM), 128, SMEM_BYTES>>>(x, out);
}

// round 15
// speedup vs baseline: 1.3012x; 1.3012x over previous
#include <cuda_runtime.h>
#include <cuda_fp16.h>
#include <cstdint>

// ---------------- problem constants -----------------------------------------
#define MROWS 8192      // B*C = 32*256
#define VIN   6890
#define VOUT  1723
#define KPAD  6912      // 108 * 64
#define NPAD  1792      // 14 * 128

// fp16 scratch (device globals; no runtime allocation)
__device__ __align__(16) __half g_Xh[(size_t)MROWS * KPAD];  // ~113 MB
__device__ __align__(16) __half g_Mh[(size_t)NPAD  * KPAD];  // ~25 MB

// ---------------- fused fp32 -> fp16 conversion (X and M in one launch) -----
// rows [0, MROWS) -> X ; rows [MROWS, MROWS+NPAD) -> M (zero-padded past VOUT)
__global__ void convert_all_v(const float* __restrict__ x,
                              const float* __restrict__ m) {
    int k8 = blockIdx.x * blockDim.x + threadIdx.x;   // 8-element K group
    if (k8 >= KPAD / 8) return;
    int row = blockIdx.y;
    int k = k8 * 8;
    __align__(16) __half h[8];

    const float* src;
    __half* dst;
    bool valid_row;
    if (row < MROWS) {
        src = x + (size_t)row * VIN + k;
        dst = &g_Xh[(size_t)row * KPAD + k];
        valid_row = true;
    } else {
        int mrow = row - MROWS;
        src = m + (size_t)mrow * VIN + k;
        dst = &g_Mh[(size_t)mrow * KPAD + k];
        valid_row = (mrow < VOUT);
    }

    if (valid_row) {
        if (k + 8 <= VIN) {
            #pragma unroll
            for (int j = 0; j < 4; ++j) {
                float2 f = *reinterpret_cast<const float2*>(src + 2 * j);
                h[2 * j]     = __float2half(f.x);
                h[2 * j + 1] = __float2half(f.y);
            }
        } else {
            #pragma unroll
            for (int j = 0; j < 8; ++j)
                h[j] = (k + j < VIN) ? __float2half(src[j]) : __float2half(0.0f);
        }
    } else {
        #pragma unroll
        for (int j = 0; j < 8; ++j) h[j] = __float2half(0.0f);
    }
    *reinterpret_cast<uint4*>(dst) = *reinterpret_cast<const uint4*>(h);
}

// ---------------- PTX helpers -----------------------------------------------
__device__ __forceinline__ void cp_async16(void* smem, const void* gmem) {
    uint32_t s = (uint32_t)__cvta_generic_to_shared(smem);
    asm volatile("cp.async.cg.shared.global [%0], [%1], 16;\n" :: "r"(s), "l"(gmem));
}
__device__ __forceinline__ void cp_commit() {
    asm volatile("cp.async.commit_group;\n" ::: "memory");
}
template<int N> __device__ __forceinline__ void cp_wait() {
    asm volatile("cp.async.wait_group %0;\n" :: "n"(N) : "memory");
}
__device__ __forceinline__ void ldsm_x4(uint32_t& r0, uint32_t& r1, uint32_t& r2,
                                        uint32_t& r3, const void* p) {
    uint32_t s = (uint32_t)__cvta_generic_to_shared(p);
    asm volatile("ldmatrix.sync.aligned.m8n8.x4.shared.b16 {%0,%1,%2,%3}, [%4];\n"
                 : "=r"(r0), "=r"(r1), "=r"(r2), "=r"(r3) : "r"(s));
}
__device__ __forceinline__ void mma16816(float* c, const uint32_t* a, const uint32_t* b) {
    asm volatile("mma.sync.aligned.m16n8k16.row.col.f32.f16.f16.f32 "
                 "{%0,%1,%2,%3}, {%4,%5,%6,%7}, {%8,%9}, {%0,%1,%2,%3};\n"
                 : "+f"(c[0]), "+f"(c[1]), "+f"(c[2]), "+f"(c[3])
                 : "r"(a[0]), "r"(a[1]), "r"(a[2]), "r"(a[3]),
                   "r"(b[0]), "r"(b[1]));
}

// ---------------- GEMM: C[8192,1723] = Xh * Mh^T (R11 core, byte-optimal) ---
// CTA tile 128x128, 4 warps (2x2), warp tile 64x64, 128 thr/CTA, occ 2.
// Measured at ~98% of the smem/L1 wavefront floor -- do not touch.
#define BM 128
#define BN 128
#define KC 64
#define STAGES 3
#define NSTG (KPAD / KC)        // 108
#define LDS_K 72                // 64 + 8 pad halves: LDSM conflict-free
#define A_HALVES (BM * LDS_K)   // 9216
#define B_HALVES (BN * LDS_K)   // 9216
#define STG_HALVES (A_HALVES + B_HALVES)       // 18432
#define SMEM_BYTES (STAGES * STG_HALVES * 2)   // 110,592 B per CTA

__global__ __launch_bounds__(128, 2) void gemm_kernel(float* __restrict__ out) {
    extern __shared__ __align__(16) __half sm[];

    const int tid  = threadIdx.x;
    const int lane = tid & 31;
    const int warp = tid >> 5;    // 0..3
    const int wm   = warp & 1;    // m offset wm*64
    const int wn   = warp >> 1;   // n offset wn*64
    const int bn   = blockIdx.x * BN;
    const int bm   = blockIdx.y * BM;

    const __half* Ag = g_Xh + (size_t)bm * KPAD;
    const __half* Bg = g_Mh + (size_t)bn * KPAD;

    auto loadStage = [&](int s) {
        __half* aS = sm + (s % STAGES) * STG_HALVES;
        __half* bS = aS + A_HALVES;
        const int kb = s * KC;
        #pragma unroll
        for (int i = 0; i < 8; ++i) {          // A: 1024 chunks / 128 thr
            const int c = tid + i * 128;
            const int r = c >> 3, k16 = c & 7;
            cp_async16(aS + r * LDS_K + k16 * 8,
                       Ag + (size_t)r * KPAD + kb + k16 * 8);
        }
        #pragma unroll
        for (int i = 0; i < 8; ++i) {          // B: 1024 chunks / 128 thr
            const int c = tid + i * 128;
            const int r = c >> 3, k16 = c & 7;
            cp_async16(bS + r * LDS_K + k16 * 8,
                       Bg + (size_t)r * KPAD + kb + k16 * 8);
        }
    };

    // double-buffered fragments (ks-level software pipeline)
    uint32_t afr[2][4][4];
    uint32_t bfr[2][8][2];

    const int a_row    = wm * 64 + (lane & 15);
    const int a_colsel = (lane >> 4) * 8;
    const int b_row    = wn * 64 + (lane & 7) + ((lane >> 4) << 3);
    const int b_colsel = ((lane >> 3) & 1) << 3;

    auto loadFrags = [&](const __half* aS, const __half* bS, int ks, int buf) {
        const int kstep = ks * 16;
        #pragma unroll
        for (int i = 0; i < 4; ++i)
            ldsm_x4(afr[buf][i][0], afr[buf][i][1], afr[buf][i][2], afr[buf][i][3],
                    aS + (a_row + i * 16) * LDS_K + kstep + a_colsel);
        #pragma unroll
        for (int j = 0; j < 4; ++j) {
            uint32_t t0, t1, t2, t3;
            ldsm_x4(t0, t1, t2, t3,
                    bS + (b_row + j * 16) * LDS_K + kstep + b_colsel);
            bfr[buf][2 * j][0] = t0;     bfr[buf][2 * j][1] = t1;
            bfr[buf][2 * j + 1][0] = t2; bfr[buf][2 * j + 1][1] = t3;
        }
    };

    float acc[4][8][4];
    #pragma unroll
    for (int i = 0; i < 4; ++i)
        #pragma unroll
        for (int j = 0; j < 8; ++j)
            #pragma unroll
            for (int e = 0; e < 4; ++e) acc[i][j][e] = 0.0f;

    loadStage(0); cp_commit();
    loadStage(1); cp_commit();
    cp_wait<1>();
    __syncthreads();               // stage 0 resident

    for (int kt = 0; kt < NSTG; ++kt) {
        if (kt + 2 < NSTG) loadStage(kt + 2);
        cp_commit();

        const __half* aS = sm + (kt % STAGES) * STG_HALVES;
        const __half* bS = aS + A_HALVES;

        loadFrags(aS, bS, 0, 0);   // prime ks=0
        #pragma unroll
        for (int ks = 0; ks < 4; ++ks) {
            const int cur = ks & 1;
            if (ks < 3) loadFrags(aS, bS, ks + 1, cur ^ 1);
            #pragma unroll
            for (int i = 0; i < 4; ++i)
                #pragma unroll
                for (int jn = 0; jn < 8; ++jn)
                    mma16816(acc[i][jn], afr[cur][i], bfr[cur][jn]);
        }

        cp_wait<1>();
        __syncthreads();           // stage kt+1 resident; all warps done with kt
    }

    // epilogue: scalar fp32 guarded stores (VOUT=1723 odd)
    const int g  = lane >> 2;
    const int tc = lane & 3;
    #pragma unroll
    for (int i = 0; i < 4; ++i) {
        #pragma unroll
        for (int jn = 0; jn < 8; ++jn) {
            const int row = bm + wm * 64 + i * 16 + g;
            const int col = bn + wn * 64 + jn * 8 + tc * 2;
            if (col < VOUT)     out[(size_t)row * VOUT + col]           = acc[i][jn][0];
            if (col + 1 < VOUT) out[(size_t)row * VOUT + col + 1]       = acc[i][jn][1];
            if (col < VOUT)     out[(size_t)(row + 8) * VOUT + col]     = acc[i][jn][2];
            if (col + 1 < VOUT) out[(size_t)(row + 8) * VOUT + col + 1] = acc[i][jn][3];
        }
    }
}

// ---------------- entry ------------------------------------------------------
extern "C" void kernel_launch(void* const* d_in, const int* in_sizes, int n_in,
                              void* d_out, int out_size) {
    const float* x = (const float*)d_in[0];  // (32,256,6890) fp32
    const float* M = (const float*)d_in[1];  // (1723,6890) fp32
    float* out = (float*)d_out;              // (32,256,1723) fp32

    cudaFuncSetAttribute(gemm_kernel, cudaFuncAttributeMaxDynamicSharedMemorySize,
                         SMEM_BYTES);

    convert_all_v<<<dim3((KPAD / 8 + 127) / 128, MROWS + NPAD), 128>>>(x, M);
    gemm_kernel<<<dim3(NPAD / BN, MROWS / BM), 128, SMEM_BYTES>>>(out);
}

// round 16
// speedup vs baseline: 1.6096x; 1.2370x over previous
#include <cuda_runtime.h>
#include <cuda_fp16.h>
#include <cstdint>

// ---------------- problem constants -----------------------------------------
#define MROWS 8192      // B*C = 32*256
#define VIN   6890
#define VOUT  1723
#define KPAD  6912      // 108 * 64
#define NPAD  1792      // 14 * 128

// fp16 scratch (device globals; no runtime allocation)
__device__ __align__(16) __half g_Xh[(size_t)MROWS * KPAD];  // ~113 MB
__device__ __align__(16) __half g_Mh[(size_t)NPAD  * KPAD];  // ~25 MB

// ---------------- fused fp32 -> fp16 conversion (X and M in one launch) -----
__global__ void convert_all_v(const float* __restrict__ x,
                              const float* __restrict__ m) {
    int k8 = blockIdx.x * blockDim.x + threadIdx.x;   // 8-element K group
    if (k8 >= KPAD / 8) return;
    int row = blockIdx.y;
    int k = k8 * 8;
    __align__(16) __half h[8];

    const float* src;
    __half* dst;
    bool valid_row;
    if (row < MROWS) {
        src = x + (size_t)row * VIN + k;
        dst = &g_Xh[(size_t)row * KPAD + k];
        valid_row = true;
    } else {
        int mrow = row - MROWS;
        src = m + (size_t)mrow * VIN + k;
        dst = &g_Mh[(size_t)mrow * KPAD + k];
        valid_row = (mrow < VOUT);
    }

    if (valid_row) {
        if (k + 8 <= VIN) {
            #pragma unroll
            for (int j = 0; j < 4; ++j) {
                float2 f = *reinterpret_cast<const float2*>(src + 2 * j);
                h[2 * j]     = __float2half(f.x);
                h[2 * j + 1] = __float2half(f.y);
            }
        } else {
            #pragma unroll
            for (int j = 0; j < 8; ++j)
                h[j] = (k + j < VIN) ? __float2half(src[j]) : __float2half(0.0f);
        }
    } else {
        #pragma unroll
        for (int j = 0; j < 8; ++j) h[j] = __float2half(0.0f);
    }
    *reinterpret_cast<uint4*>(dst) = *reinterpret_cast<const uint4*>(h);
}

// ---------------- PTX helpers -----------------------------------------------
__device__ __forceinline__ void cp_async16(void* smem, const void* gmem) {
    uint32_t s = (uint32_t)__cvta_generic_to_shared(smem);
    asm volatile("cp.async.cg.shared.global [%0], [%1], 16;\n" :: "r"(s), "l"(gmem));
}
__device__ __forceinline__ void cp_commit() {
    asm volatile("cp.async.commit_group;\n" ::: "memory");
}
template<int N> __device__ __forceinline__ void cp_wait() {
    asm volatile("cp.async.wait_group %0;\n" :: "n"(N) : "memory");
}
__device__ __forceinline__ void ldsm_x4(uint32_t& r0, uint32_t& r1, uint32_t& r2,
                                        uint32_t& r3, const void* p) {
    uint32_t s = (uint32_t)__cvta_generic_to_shared(p);
    asm volatile("ldmatrix.sync.aligned.m8n8.x4.shared.b16 {%0,%1,%2,%3}, [%4];\n"
                 : "=r"(r0), "=r"(r1), "=r"(r2), "=r"(r3) : "r"(s));
}
__device__ __forceinline__ void mma16816(float* c, const uint32_t* a, const uint32_t* b) {
    asm volatile("mma.sync.aligned.m16n8k16.row.col.f32.f16.f16.f32 "
                 "{%0,%1,%2,%3}, {%4,%5,%6,%7}, {%8,%9}, {%0,%1,%2,%3};\n"
                 : "+f"(c[0]), "+f"(c[1]), "+f"(c[2]), "+f"(c[3])
                 : "r"(a[0]), "r"(a[1]), "r"(a[2]), "r"(a[3]),
                   "r"(b[0]), "r"(b[1]));
}

// ---------------- GEMM: C[8192,1723] = Xh * Mh^T -----------------------------
// R15 core (CTA 128x128, 4 warps 64x64, 3-stage, occ 2) with the per-kt
// head-of-iteration bubble drained: fragment prime is the first op after the
// barrier, and the 16 cp.async of stage kt+2 are spread 4-per-ks so their
// MIO issue cost hides under the MMA blocks.
#define BM 128
#define BN 128
#define KC 64
#define STAGES 3
#define NSTG (KPAD / KC)        // 108
#define LDS_K 72                // 64 + 8 pad halves: LDSM conflict-free
#define A_HALVES (BM * LDS_K)   // 9216
#define B_HALVES (BN * LDS_K)   // 9216
#define STG_HALVES (A_HALVES + B_HALVES)       // 18432
#define SMEM_BYTES (STAGES * STG_HALVES * 2)   // 110,592 B per CTA

__global__ __launch_bounds__(128, 2) void gemm_kernel(float* __restrict__ out) {
    extern __shared__ __align__(16) __half sm[];

    const int tid  = threadIdx.x;
    const int lane = tid & 31;
    const int warp = tid >> 5;    // 0..3
    const int wm   = warp & 1;    // m offset wm*64
    const int wn   = warp >> 1;   // n offset wn*64
    const int bn   = blockIdx.x * BN;
    const int bm   = blockIdx.y * BM;

    const __half* Ag = g_Xh + (size_t)bm * KPAD;
    const __half* Bg = g_Mh + (size_t)bn * KPAD;

    // full-stage fill (prologue only)
    auto loadStage = [&](int s) {
        __half* aS = sm + (s % STAGES) * STG_HALVES;
        __half* bS = aS + A_HALVES;
        const int kb = s * KC;
        #pragma unroll
        for (int i = 0; i < 8; ++i) {
            const int c = tid + i * 128;
            const int r = c >> 3, k16 = c & 7;
            cp_async16(aS + r * LDS_K + k16 * 8,
                       Ag + (size_t)r * KPAD + kb + k16 * 8);
        }
        #pragma unroll
        for (int i = 0; i < 8; ++i) {
            const int c = tid + i * 128;
            const int r = c >> 3, k16 = c & 7;
            cp_async16(bS + r * LDS_K + k16 * 8,
                       Bg + (size_t)r * KPAD + kb + k16 * 8);
        }
    };

    // quarter-stage fill: 2 A-chunks + 2 B-chunks per thread (q = 0..3)
    auto loadQuarter = [&](int s, int q) {
        __half* aS = sm + (s % STAGES) * STG_HALVES;
        __half* bS = aS + A_HALVES;
        const int kb = s * KC;
        #pragma unroll
        for (int i = 2 * q; i < 2 * q + 2; ++i) {
            const int c = tid + i * 128;
            const int r = c >> 3, k16 = c & 7;
            cp_async16(aS + r * LDS_K + k16 * 8,
                       Ag + (size_t)r * KPAD + kb + k16 * 8);
        }
        #pragma unroll
        for (int i = 2 * q; i < 2 * q + 2; ++i) {
            const int c = tid + i * 128;
            const int r = c >> 3, k16 = c & 7;
            cp_async16(bS + r * LDS_K + k16 * 8,
                       Bg + (size_t)r * KPAD + kb + k16 * 8);
        }
    };

    // double-buffered fragments (ks-level software pipeline)
    uint32_t afr[2][4][4];
    uint32_t bfr[2][8][2];

    const int a_row    = wm * 64 + (lane & 15);
    const int a_colsel = (lane >> 4) * 8;
    const int b_row    = wn * 64 + (lane & 7) + ((lane >> 4) << 3);
    const int b_colsel = ((lane >> 3) & 1) << 3;

    auto loadFrags = [&](const __half* aS, const __half* bS, int ks, int buf) {
        const int kstep = ks * 16;
        #pragma unroll
        for (int i = 0; i < 4; ++i)
            ldsm_x4(afr[buf][i][0], afr[buf][i][1], afr[buf][i][2], afr[buf][i][3],
                    aS + (a_row + i * 16) * LDS_K + kstep + a_colsel);
        #pragma unroll
        for (int j = 0; j < 4; ++j) {
            uint32_t t0, t1, t2, t3;
            ldsm_x4(t0, t1, t2, t3,
                    bS + (b_row + j * 16) * LDS_K + kstep + b_colsel);
            bfr[buf][2 * j][0] = t0;     bfr[buf][2 * j][1] = t1;
            bfr[buf][2 * j + 1][0] = t2; bfr[buf][2 * j + 1][1] = t3;
        }
    };

    float acc[4][8][4];
    #pragma unroll
    for (int i = 0; i < 4; ++i)
        #pragma unroll
        for (int j = 0; j < 8; ++j)
            #pragma unroll
            for (int e = 0; e < 4; ++e) acc[i][j][e] = 0.0f;

    loadStage(0); cp_commit();
    loadStage(1); cp_commit();
    cp_wait<1>();
    __syncthreads();               // stage 0 resident

    for (int kt = 0; kt < NSTG; ++kt) {
        const bool doL = (kt + 2 < NSTG);
        const __half* aS = sm + (kt % STAGES) * STG_HALVES;
        const __half* bS = aS + A_HALVES;

        // FIRST op after the barrier: restart the tensor-feeding path
        loadFrags(aS, bS, 0, 0);

        #pragma unroll
        for (int ks = 0; ks < 4; ++ks) {
            const int cur = ks & 1;
            if (ks < 3) loadFrags(aS, bS, ks + 1, cur ^ 1);
            if (doL) loadQuarter(kt + 2, ks);   // 4 cp.async hidden under MMAs
            #pragma unroll
            for (int i = 0; i < 4; ++i)
                #pragma unroll
                for (int jn = 0; jn < 8; ++jn)
                    mma16816(acc[i][jn], afr[cur][i], bfr[cur][jn]);
        }

        cp_commit();               // one group per kt (may be empty at the tail)
        cp_wait<1>();
        __syncthreads();           // stage kt+1 resident; all warps done with kt
    }

    // epilogue: scalar fp32 guarded stores (VOUT=1723 odd)
    const int g  = lane >> 2;
    const int tc = lane & 3;
    #pragma unroll
    for (int i = 0; i < 4; ++i) {
        #pragma unroll
        for (int jn = 0; jn < 8; ++jn) {
            const int row = bm + wm * 64 + i * 16 + g;
            const int col = bn + wn * 64 + jn * 8 + tc * 2;
            if (col < VOUT)     out[(size_t)row * VOUT + col]           = acc[i][jn][0];
            if (col + 1 < VOUT) out[(size_t)row * VOUT + col + 1]       = acc[i][jn][1];
            if (col < VOUT)     out[(size_t)(row + 8) * VOUT + col]     = acc[i][jn][2];
            if (col + 1 < VOUT) out[(size_t)(row + 8) * VOUT + col + 1] = acc[i][jn][3];
        }
    }
}

// ---------------- entry ------------------------------------------------------
extern "C" void kernel_launch(void* const* d_in, const int* in_sizes, int n_in,
                              void* d_out, int out_size) {
    const float* x = (const float*)d_in[0];  // (32,256,6890) fp32
    const float* M = (const float*)d_in[1];  // (1723,6890) fp32
    float* out = (float*)d_out;              // (32,256,1723) fp32

    cudaFuncSetAttribute(gemm_kernel, cudaFuncAttributeMaxDynamicSharedMemorySize,
                         SMEM_BYTES);

    convert_all_v<<<dim3((KPAD / 8 + 127) / 128, MROWS + NPAD), 128>>>(x, M);
    gemm_kernel<<<dim3(NPAD / BN, MROWS / BM), 128, SMEM_BYTES>>>(out);
}